// round 4
// baseline (speedup 1.0000x reference)
#include <cuda_runtime.h>

// ---------------- scratch (static device globals; no allocation) ----------------
__device__ float g_y1[32 * 24 * 32 * 32];   // conv1 raw output (pre-BN)
__device__ float g_y2[32 * 24 * 16 * 16];   // conv2 raw output (pre-BN)
__device__ float g_part1s[24 * 128];        // conv1 per-block channel sums
__device__ float g_part1q[24 * 128];
__device__ float g_part2s[24 * 32];
__device__ float g_part2q[24 * 32];
__device__ float g_hpart[32 * 8 * 2];       // per-(n,chunk) fc2 partials
__device__ unsigned g_bar_count;            // zero-init, self-cleaning
__device__ volatile unsigned g_bar_gen;

#define NBLOCKS 256

__device__ __forceinline__ float warp_sum(float v) {
#pragma unroll
    for (int o = 16; o > 0; o >>= 1) v += __shfl_down_sync(0xffffffffu, v, o);
    return v;
}

// Software grid barrier: 256 blocks, 2 per SM co-resident (smem 37.6KB*2 < 228KB).
__device__ __forceinline__ void grid_barrier() {
    __syncthreads();
    if (threadIdx.x == 0) {
        __threadfence();
        unsigned gen = g_bar_gen;
        unsigned ticket = atomicAdd(&g_bar_count, 1u);
        if (ticket == NBLOCKS - 1) {
            g_bar_count = 0;
            __threadfence();
            g_bar_gen = gen + 1;
        } else {
            while (g_bar_gen == gen) { __nanosleep(32); }
        }
        __threadfence();
    }
    __syncthreads();
}

// Distributed BN finalize: every block computes 24 folded affine consts itself.
__device__ __forceinline__ void compute_bn24(const float* __restrict__ ps,
                                             const float* __restrict__ pq,
                                             int np, float invM,
                                             const float* __restrict__ gamma,
                                             const float* __restrict__ beta,
                                             float* s_a, float* s_c, int t) {
    if (t < 192) {
        int c = t >> 3, g = t & 7;
        float s = 0.f, q = 0.f;
        for (int i = g; i < np; i += 8) { s += ps[c * np + i]; q += pq[c * np + i]; }
#pragma unroll
        for (int o = 4; o > 0; o >>= 1) {
            s += __shfl_down_sync(0xffffffffu, s, o, 8);
            q += __shfl_down_sync(0xffffffffu, q, o, 8);
        }
        if (g == 0) {
            float mean = s * invM;
            float var  = q * invM - mean * mean;
            float a    = gamma[c] * rsqrtf(var + 1e-5f);
            s_a[c] = a;
            s_c[c] = beta[c] - mean * a;
        }
    }
}

// ------------------------- fused persistent kernel -------------------------
__global__ void __launch_bounds__(256, 2) fused_kernel(
    const float* __restrict__ image, const float* __restrict__ w1,
    const float* __restrict__ bn1_g, const float* __restrict__ bn1_b,
    const float* __restrict__ w2, const float* __restrict__ bn2_g,
    const float* __restrict__ bn2_b, const float* __restrict__ ques,
    const float* __restrict__ w_rel, const float* __restrict__ b_rel,
    const float* __restrict__ w_fc1, const float* __restrict__ b_fc1,
    const float* __restrict__ w_fc2, const float* __restrict__ b_fc2,
    float* __restrict__ out) {

    __shared__ __align__(16) float smem[9408];
    const int bid = blockIdx.x;
    const int t = threadIdx.x;
    const int warp = t >> 5, lane = t & 31;

    // ============================ PHASE 1: conv1 ============================
    // 256 blocks: n = bid>>3, quarter q = (bid>>1)&3 (8 out rows), cb = (bid&1)*12
    {
        const int n = bid >> 3;
        const int q = (bid >> 1) & 3;
        const int cb = (bid & 1) * 12;
        float* s_in = smem;                       // [3][17][65]  (3315)
        float* s_w  = smem + 3328;                // [(ci*3+kh)][40] (360)
        float* s_rd = smem + 3696;                // [12][8][2]

        // stage input rows 16q-1 .. 16q+15, col 0 zero-padded
        for (int idx = t; idx < 3 * 17 * 64; idx += 256) {
            int c   = idx / 1088;
            int rem = idx - c * 1088;
            int r   = rem >> 6;
            int w   = rem & 63;
            int hg  = 16 * q - 1 + r;
            float v = 0.f;
            if (hg >= 0) v = image[((n * 3 + c) * 64 + hg) * 64 + w];
            s_in[c * 1105 + r * 65 + w + 1] = v;
        }
        if (t < 51) s_in[(t / 17) * 1105 + (t % 17) * 65] = 0.f;
        // weights: [ci][kh][co*3+kw] padded to 40 per (ci,kh) -- strided, 324 items!
        for (int idx = t; idx < 324; idx += 256) {
            int co = idx / 27;
            int rem = idx % 27;
            int ci = rem / 9, kh = (rem % 9) / 3, kw = rem % 3;
            s_w[(ci * 3 + kh) * 40 + co * 3 + kw] = w1[(cb + co) * 27 + rem];
        }
        __syncthreads();

        const int r = t >> 5, wo = t & 31;   // 8 rows x 32 cols, 1 px/thread
        float acc[12];
#pragma unroll
        for (int co = 0; co < 12; co++) acc[co] = 0.f;

#pragma unroll 1
        for (int ci = 0; ci < 3; ci++) {
#pragma unroll
            for (int kh = 0; kh < 3; kh++) {
                const float* ip = &s_in[ci * 1105 + (2 * r + kh) * 65 + 2 * wo];
                float v0 = ip[0], v1 = ip[1], v2 = ip[2];
                const float4* wp = reinterpret_cast<const float4*>(&s_w[(ci * 3 + kh) * 40]);
#pragma unroll
                for (int c4 = 0; c4 < 3; c4++) {
                    float4 a = wp[c4 * 3], b = wp[c4 * 3 + 1], c = wp[c4 * 3 + 2];
                    acc[4 * c4 + 0] += v0 * a.x + v1 * a.y + v2 * a.z;
                    acc[4 * c4 + 1] += v0 * a.w + v1 * b.x + v2 * b.y;
                    acc[4 * c4 + 2] += v0 * b.z + v1 * b.w + v2 * c.x;
                    acc[4 * c4 + 3] += v0 * c.y + v1 * c.z + v2 * c.w;
                }
            }
        }

#pragma unroll
        for (int co = 0; co < 12; co++)
            g_y1[((n * 24 + cb + co) * 32 + q * 8 + r) * 32 + wo] = acc[co];

#pragma unroll
        for (int co = 0; co < 12; co++) {
            float rs = warp_sum(acc[co]);
            float rq = warp_sum(acc[co] * acc[co]);
            if (lane == 0) { s_rd[co * 16 + warp * 2] = rs; s_rd[co * 16 + warp * 2 + 1] = rq; }
        }
        __syncthreads();
        if (t < 12) {
            float s = 0.f, qq = 0.f;
#pragma unroll
            for (int w = 0; w < 8; w++) { s += s_rd[t * 16 + w * 2]; qq += s_rd[t * 16 + w * 2 + 1]; }
            g_part1s[(cb + t) * 128 + n * 4 + q] = s;
            g_part1q[(cb + t) * 128 + n * 4 + q] = qq;
        }
    }

    grid_barrier();

    // ============================ PHASE 2: conv2 ============================
    // 256 blocks: n = bid>>3, cb = (bid&7)*3
    {
        const int n = bid >> 3;
        const int cb = (bid & 7) * 3;
        float* s_in = smem;                       // [8][33][33] (8712)
        float* s_w  = smem + 8712;                // [(ci8*3+kh)][12] (288)
        float* s_a  = smem + 9000;
        float* s_c  = smem + 9024;
        float* s_rd = smem + 9048;                // [3][8][2]

        compute_bn24(g_part1s, g_part1q, 128, 1.f / 32768.f, bn1_g, bn1_b, s_a, s_c, t);

        const int ho = t >> 4, wo = t & 15;
        float acc0 = 0.f, acc1 = 0.f, acc2 = 0.f;

#pragma unroll 1
        for (int ph = 0; ph < 3; ph++) {
            const int cc = ph * 8;
            __syncthreads();
            for (int idx = t; idx < 264; idx += 256) {
                int ci = idx / 33, k = idx % 33;
                s_in[ci * 1089 + k] = 0.f;        // row 0
                s_in[ci * 1089 + k * 33] = 0.f;   // col 0
            }
            for (int idx = t; idx < 8192; idx += 256) {
                int ci8 = idx >> 10;
                int rem = idx & 1023;
                int h = rem >> 5, w = rem & 31;
                float y = g_y1[((n * 24 + cc + ci8) * 32 + h) * 32 + w];
                float f = fmaxf(fmaf(s_a[cc + ci8], y, s_c[cc + ci8]), 0.f);
                s_in[ci8 * 1089 + (h + 1) * 33 + (w + 1)] = f;
            }
            // weights this phase: 3co x 8ci x 9 = 216 -> [(ci8*3+kh)][co*3+kw] pad 12
            if (t < 216) {
                int co = t / 72;
                int r = t % 72;
                int ci8 = r / 9, kh = (r % 9) / 3, kw = r % 3;
                s_w[(ci8 * 3 + kh) * 12 + co * 3 + kw] =
                    w2[((cb + co) * 24 + cc + ci8) * 9 + kh * 3 + kw];
            }
            __syncthreads();

#pragma unroll 1
            for (int ci8 = 0; ci8 < 8; ci8++) {
#pragma unroll
                for (int kh = 0; kh < 3; kh++) {
                    const float* ip = &s_in[ci8 * 1089 + (2 * ho + kh) * 33 + 2 * wo];
                    float v0 = ip[0], v1 = ip[1], v2 = ip[2];
                    const float* wb = &s_w[(ci8 * 3 + kh) * 12];
                    float4 wa = *reinterpret_cast<const float4*>(wb);
                    float4 wc = *reinterpret_cast<const float4*>(wb + 4);
                    float w8 = wb[8];
                    acc0 += v0 * wa.x + v1 * wa.y + v2 * wa.z;
                    acc1 += v0 * wa.w + v1 * wc.x + v2 * wc.y;
                    acc2 += v0 * wc.z + v1 * wc.w + v2 * w8;
                }
            }
        }

        g_y2[((n * 24 + cb + 0) * 16 + ho) * 16 + wo] = acc0;
        g_y2[((n * 24 + cb + 1) * 16 + ho) * 16 + wo] = acc1;
        g_y2[((n * 24 + cb + 2) * 16 + ho) * 16 + wo] = acc2;

        float av[3] = {acc0, acc1, acc2};
#pragma unroll
        for (int c3 = 0; c3 < 3; c3++) {
            float rs = warp_sum(av[c3]);
            float rq = warp_sum(av[c3] * av[c3]);
            if (lane == 0) { s_rd[c3 * 16 + warp * 2] = rs; s_rd[c3 * 16 + warp * 2 + 1] = rq; }
        }
        __syncthreads();
        if (t < 3) {
            float s = 0.f, qq = 0.f;
#pragma unroll
            for (int w = 0; w < 8; w++) { s += s_rd[t * 16 + w * 2]; qq += s_rd[t * 16 + w * 2 + 1]; }
            g_part2s[(cb + t) * 32 + n] = s;
            g_part2q[(cb + t) * 32 + n] = qq;
        }
    }

    grid_barrier();

    // ============================ PHASE 3a: head ============================
    // 256 blocks: n = bid>>3, chunk = bid&7 (128 fc1 outputs each)
    {
        const int n = bid >> 3;
        const int chunk = bid & 7;
        float* s_q     = smem;            // 128
        float* s_a2    = smem + 128;      // 24
        float* s_c2    = smem + 152;      // 24
        float* s_part  = smem + 176;      // 24*8
        float* s_s     = smem + 368;      // 26 (pad 32)
        float* s_r     = smem + 400;      // 128
        float* s_hpart = smem + 528;      // 256
        float* s_o     = smem + 784;      // 8

        compute_bn24(g_part2s, g_part2q, 32, 1.f / 8192.f, bn2_g, bn2_b, s_a2, s_c2, t);
        if (t >= 192) {
            int j = t - 192;
            s_q[j * 2]     = ques[n * 128 + j * 2];
            s_q[j * 2 + 1] = ques[n * 128 + j * 2 + 1];
        }
        __syncthreads();

        // spatial sums of relu(bn2(y2)) -> s[0..23]; coord sums ~0 -> 0
        if (t < 192) {
            int c = t >> 3, g = t & 7;
            const float* yp = &g_y2[(n * 24 + c) * 256 + g * 32];
            float a = s_a2[c], cc = s_c2[c];
            float acc = 0.f;
#pragma unroll
            for (int i = 0; i < 32; i++) acc += fmaxf(fmaf(a, yp[i], cc), 0.f);
            s_part[c * 8 + g] = acc;
        }
        __syncthreads();
        if (t < 26) {
            float s = 0.f;
            if (t < 24) {
#pragma unroll
                for (int g = 0; g < 8; g++) s += s_part[t * 8 + g];
            }
            s_s[t] = s;
        }
        __syncthreads();

        // relations[j] = 256 * s.(Wi+Wj)[:,j] + 65536 * (q.Wq[:,j] + b_rel[j])
        if (t < 128) {
            const int j = t;
            float r1 = 0.f;
#pragma unroll
            for (int k = 0; k < 26; k++)
                r1 += s_s[k] * (w_rel[k * 128 + j] + w_rel[(26 + k) * 128 + j]);
            float r2 = b_rel[j];
#pragma unroll 8
            for (int q = 0; q < 128; q++)
                r2 = fmaf(s_q[q], w_rel[(52 + q) * 128 + j], r2);
            s_r[j] = 256.f * r1 + 65536.f * r2;
        }
        __syncthreads();

        // fc1 chunk: outputs j0+jj, k split in halves across thread pairs
        {
            const int jj = t & 127, h = t >> 7;
            const int j = chunk * 128 + jj;
            float acc = (h == 0) ? b_fc1[j] : 0.f;
            const float* wp = &w_fc1[(h * 64) * 1024 + j];
            const float* rp = &s_r[h * 64];
#pragma unroll 8
            for (int k = 0; k < 64; k++)
                acc = fmaf(rp[k], wp[k * 1024], acc);
            s_hpart[t] = acc;
        }
        __syncthreads();
        // relu + partial fc2 over this chunk's 128 h values
        {
            float p0 = 0.f, p1 = 0.f;
            if (t < 128) {
                float hv = fmaxf(s_hpart[t] + s_hpart[t + 128], 0.f);
                const int j = chunk * 128 + t;
                p0 = hv * w_fc2[j * 2];
                p1 = hv * w_fc2[j * 2 + 1];
            }
            p0 = warp_sum(p0);
            p1 = warp_sum(p1);
            if (lane == 0 && warp < 4) { s_o[warp * 2] = p0; s_o[warp * 2 + 1] = p1; }
        }
        __syncthreads();
        if (t == 0) {
            float o0 = 0.f, o1 = 0.f;
#pragma unroll
            for (int w = 0; w < 4; w++) { o0 += s_o[w * 2]; o1 += s_o[w * 2 + 1]; }
            g_hpart[(n * 8 + chunk) * 2 + 0] = o0;
            g_hpart[(n * 8 + chunk) * 2 + 1] = o1;
        }
    }

    grid_barrier();

    // ============================ PHASE 3b: final ============================
    if (bid < 32 && t < 2) {
        float o = b_fc2[t];
#pragma unroll
        for (int c = 0; c < 8; c++) o += g_hpart[(bid * 8 + c) * 2 + t];
        out[bid * 2 + t] = o;
    }
}

// ---------------- launch ----------------
extern "C" void kernel_launch(void* const* d_in, const int* in_sizes, int n_in,
                              void* d_out, int out_size) {
    (void)in_sizes; (void)n_in; (void)out_size;
    const float* image   = (const float*)d_in[0];
    const float* ques    = (const float*)d_in[1];
    const float* conv1_w = (const float*)d_in[2];
    const float* bn1_g   = (const float*)d_in[4];
    const float* bn1_b   = (const float*)d_in[5];
    const float* conv2_w = (const float*)d_in[6];
    const float* bn2_g   = (const float*)d_in[8];
    const float* bn2_b   = (const float*)d_in[9];
    const float* w_rel   = (const float*)d_in[10];
    const float* b_rel   = (const float*)d_in[11];
    const float* w_fc1   = (const float*)d_in[12];
    const float* b_fc1   = (const float*)d_in[13];
    const float* w_fc2   = (const float*)d_in[14];
    const float* b_fc2   = (const float*)d_in[15];
    float* out = (float*)d_out;

    fused_kernel<<<NBLOCKS, 256>>>(image, conv1_w, bn1_g, bn1_b,
                                   conv2_w, bn2_g, bn2_b,
                                   ques, w_rel, b_rel,
                                   w_fc1, b_fc1, w_fc2, b_fc2, out);
}

// round 5
// speedup vs baseline: 1.0054x; 1.0054x over previous
#include <cuda_runtime.h>

// ---------------- scratch (static device globals; no allocation) ----------------
__device__ float g_y1[32 * 24 * 32 * 32];   // conv1 raw output (pre-BN)
__device__ float g_y2[32 * 24 * 16 * 16];   // conv2 raw output (pre-BN)
__device__ float g_part1s[24 * 128];        // conv1 per-block channel sums
__device__ float g_part1q[24 * 128];
__device__ float g_part2s[24 * 64];         // conv2: key = n*2+half
__device__ float g_part2q[24 * 64];
__device__ float g_hpart[32 * 8 * 2];       // per-(n,chunk) fc2 partials
__device__ unsigned g_done[32];             // per-n ticket, zero-init, self-reset
__device__ unsigned g_cnt1[16 * 32];        // group counters, padded to 128B lines
__device__ unsigned g_cnt2;                 // root counter
__device__ volatile unsigned g_bar_gen;

#define NBLOCKS 256

__device__ __forceinline__ float warp_sum(float v) {
#pragma unroll
    for (int o = 16; o > 0; o >>= 1) v += __shfl_down_sync(0xffffffffu, v, o);
    return v;
}

// Two-level grid barrier: 16 groups x 16 arrivals, then 16 -> root.
// All 256 blocks co-resident (2/SM by launch_bounds, smem 34.3KB*2 < 228KB).
__device__ __forceinline__ void grid_barrier() {
    __syncthreads();
    if (threadIdx.x == 0) {
        __threadfence();
        unsigned gen = g_bar_gen;
        unsigned r = atomicAdd(&g_cnt1[(blockIdx.x >> 4) * 32], 1u);
        if (r == 15) {
            unsigned r2 = atomicAdd(&g_cnt2, 1u);
            if (r2 == 15) {
                g_cnt2 = 0;
#pragma unroll
                for (int i = 0; i < 16; i++) g_cnt1[i * 32] = 0;
                __threadfence();            // resets visible before release
                g_bar_gen = gen + 1;
            } else {
                while (g_bar_gen == gen) {}
            }
        } else {
            while (g_bar_gen == gen) {}
        }
        __threadfence();
    }
    __syncthreads();
}

// Distributed BN finalize: every block computes 24 folded affine consts itself.
__device__ __forceinline__ void compute_bn24(const float* __restrict__ ps,
                                             const float* __restrict__ pq,
                                             int np, float invM,
                                             const float* __restrict__ gamma,
                                             const float* __restrict__ beta,
                                             float* s_a, float* s_c, int t) {
    if (t < 192) {
        int c = t >> 3, g = t & 7;
        float s = 0.f, q = 0.f;
        for (int i = g; i < np; i += 8) { s += ps[c * np + i]; q += pq[c * np + i]; }
#pragma unroll
        for (int o = 4; o > 0; o >>= 1) {
            s += __shfl_down_sync(0xffffffffu, s, o, 8);
            q += __shfl_down_sync(0xffffffffu, q, o, 8);
        }
        if (g == 0) {
            float mean = s * invM;
            float var  = q * invM - mean * mean;
            float a    = gamma[c] * rsqrtf(var + 1e-5f);
            s_a[c] = a;
            s_c[c] = beta[c] - mean * a;
        }
    }
}

// ------------------------- fused persistent kernel -------------------------
__global__ void __launch_bounds__(256, 2) fused_kernel(
    const float* __restrict__ image, const float* __restrict__ w1,
    const float* __restrict__ bn1_g, const float* __restrict__ bn1_b,
    const float* __restrict__ w2, const float* __restrict__ bn2_g,
    const float* __restrict__ bn2_b, const float* __restrict__ ques,
    const float* __restrict__ w_rel, const float* __restrict__ b_rel,
    const float* __restrict__ w_fc1, const float* __restrict__ b_fc1,
    const float* __restrict__ w_fc2, const float* __restrict__ b_fc2,
    float* __restrict__ out) {

    __shared__ __align__(16) float smem[8576];
    const int bid = blockIdx.x;
    const int t = threadIdx.x;
    const int warp = t >> 5, lane = t & 31;

    // ============================ PHASE 1: conv1 ============================
    // 256 blocks: n = bid>>3, quarter q = (bid>>1)&3 (8 out rows), cb = (bid&1)*12
    {
        const int n = bid >> 3;
        const int q = (bid >> 1) & 3;
        const int cb = (bid & 1) * 12;
        float* s_in = smem;                       // [3][17][65]  (3315)
        float* s_w  = smem + 3328;                // [(ci*3+kh)][40] (360)
        float* s_rd = smem + 3696;                // [12][8][2]

        for (int idx = t; idx < 3 * 17 * 64; idx += 256) {
            int c   = idx / 1088;
            int rem = idx - c * 1088;
            int r   = rem >> 6;
            int w   = rem & 63;
            int hg  = 16 * q - 1 + r;
            float v = 0.f;
            if (hg >= 0) v = image[((n * 3 + c) * 64 + hg) * 64 + w];
            s_in[c * 1105 + r * 65 + w + 1] = v;
        }
        if (t < 51) s_in[(t / 17) * 1105 + (t % 17) * 65] = 0.f;
        for (int idx = t; idx < 324; idx += 256) {
            int co = idx / 27;
            int rem = idx % 27;
            int ci = rem / 9, kh = (rem % 9) / 3, kw = rem % 3;
            s_w[(ci * 3 + kh) * 40 + co * 3 + kw] = w1[(cb + co) * 27 + rem];
        }
        __syncthreads();

        const int r = t >> 5, wo = t & 31;   // 8 rows x 32 cols, 1 px/thread
        float acc[12];
#pragma unroll
        for (int co = 0; co < 12; co++) acc[co] = 0.f;

#pragma unroll 1
        for (int ci = 0; ci < 3; ci++) {
#pragma unroll
            for (int kh = 0; kh < 3; kh++) {
                const float* ip = &s_in[ci * 1105 + (2 * r + kh) * 65 + 2 * wo];
                float v0 = ip[0], v1 = ip[1], v2 = ip[2];
                const float4* wp = reinterpret_cast<const float4*>(&s_w[(ci * 3 + kh) * 40]);
#pragma unroll
                for (int c4 = 0; c4 < 3; c4++) {
                    float4 a = wp[c4 * 3], b = wp[c4 * 3 + 1], c = wp[c4 * 3 + 2];
                    acc[4 * c4 + 0] += v0 * a.x + v1 * a.y + v2 * a.z;
                    acc[4 * c4 + 1] += v0 * a.w + v1 * b.x + v2 * b.y;
                    acc[4 * c4 + 2] += v0 * b.z + v1 * b.w + v2 * c.x;
                    acc[4 * c4 + 3] += v0 * c.y + v1 * c.z + v2 * c.w;
                }
            }
        }

#pragma unroll
        for (int co = 0; co < 12; co++)
            g_y1[((n * 24 + cb + co) * 32 + q * 8 + r) * 32 + wo] = acc[co];

#pragma unroll
        for (int co = 0; co < 12; co++) {
            float rs = warp_sum(acc[co]);
            float rq = warp_sum(acc[co] * acc[co]);
            if (lane == 0) { s_rd[co * 16 + warp * 2] = rs; s_rd[co * 16 + warp * 2 + 1] = rq; }
        }
        __syncthreads();
        if (t < 12) {
            float s = 0.f, qq = 0.f;
#pragma unroll
            for (int w = 0; w < 8; w++) { s += s_rd[t * 16 + w * 2]; qq += s_rd[t * 16 + w * 2 + 1]; }
            g_part1s[(cb + t) * 128 + n * 4 + q] = s;
            g_part1q[(cb + t) * 128 + n * 4 + q] = qq;
        }
    }

    grid_barrier();

    // ============================ PHASE 2: conv2 ============================
    // 256 blocks: n = bid>>3, co-group cb = ((bid>>1)&3)*6, half = bid&1.
    // Each block: out rows [8*half, 8*half+8) x 16 cols x 6 channels.
    // t&127 -> pixel (r = (t&127)>>4 in 0..7, wo = t&15); hh = t>>7 -> ch triple.
    {
        const int n = bid >> 3;
        const int cb = ((bid >> 1) & 3) * 6;
        const int half = bid & 1;
        float* s_in = smem;                       // [12][17][33] (6732)
        float* s_w  = smem + 6736;                // [72][24] (1728)
        float* s_a  = smem + 8464;
        float* s_c  = smem + 8488;
        float* s_rd = smem + 8512;                // [6][4][2]

        compute_bn24(g_part1s, g_part1q, 128, 1.f / 32768.f, bn1_g, bn1_b, s_a, s_c, t);

        // stage all weights once: dst [(ci*3+kh)*24 + hh*12 + c3*3 + kw]
        for (int idx = t; idx < 1296; idx += 256) {
            int ci = idx / 54;
            int rem = idx % 54;
            int kh = rem / 18;
            int ch = (rem % 18) / 3;
            int kw = rem % 3;
            s_w[(ci * 3 + kh) * 24 + (ch / 3) * 12 + (ch % 3) * 3 + kw] =
                w2[((cb + ch) * 24 + ci) * 9 + kh * 3 + kw];
        }

        const int px = t & 127;
        const int r = px >> 4, wo = px & 15;
        const int hh = t >> 7;
        float acc0 = 0.f, acc1 = 0.f, acc2 = 0.f;

#pragma unroll 1
        for (int ph = 0; ph < 2; ph++) {
            const int cc = ph * 12;
            __syncthreads();   // first iter: weights+BN consts; later: s_in reuse
            // stage y1 rows 16*half-1 .. 16*half+15 for 12 channels, BN+ReLU
            for (int idx = t; idx < 12 * 17 * 32; idx += 256) {
                int ci  = idx / 544;
                int rem = idx - ci * 544;
                int rr  = rem >> 5, w = rem & 31;
                int row = 16 * half - 1 + rr;
                float f = 0.f;
                if (row >= 0) {
                    float y = g_y1[((n * 24 + cc + ci) * 32 + row) * 32 + w];
                    f = fmaxf(fmaf(s_a[cc + ci], y, s_c[cc + ci]), 0.f);
                }
                s_in[ci * 561 + rr * 33 + w + 1] = f;
            }
            if (t < 204) s_in[(t / 17) * 561 + (t % 17) * 33] = 0.f;  // col 0 pad
            __syncthreads();

#pragma unroll 1
            for (int ci = 0; ci < 12; ci++) {
#pragma unroll
                for (int kh = 0; kh < 3; kh++) {
                    const float* ip = &s_in[ci * 561 + (2 * r + kh) * 33 + 2 * wo];
                    float v0 = ip[0], v1 = ip[1], v2 = ip[2];
                    const float* wb = &s_w[((cc + ci) * 3 + kh) * 24 + hh * 12];
                    float4 wa = *reinterpret_cast<const float4*>(wb);
                    float4 wc = *reinterpret_cast<const float4*>(wb + 4);
                    float w8 = wb[8];
                    acc0 += v0 * wa.x + v1 * wa.y + v2 * wa.z;
                    acc1 += v0 * wa.w + v1 * wc.x + v2 * wc.y;
                    acc2 += v0 * wc.z + v1 * wc.w + v2 * w8;
                }
            }
        }

        const int ho = half * 8 + r;
        g_y2[((n * 24 + cb + hh * 3 + 0) * 16 + ho) * 16 + wo] = acc0;
        g_y2[((n * 24 + cb + hh * 3 + 1) * 16 + ho) * 16 + wo] = acc1;
        g_y2[((n * 24 + cb + hh * 3 + 2) * 16 + ho) * 16 + wo] = acc2;

        // per-channel partial sums over this block's 128 px (4 warps per triple)
        float av[3] = {acc0, acc1, acc2};
#pragma unroll
        for (int c3 = 0; c3 < 3; c3++) {
            float rs = warp_sum(av[c3]);
            float rq = warp_sum(av[c3] * av[c3]);
            if (lane == 0) {
                int ch = hh * 3 + c3, w4 = warp & 3;
                s_rd[ch * 8 + w4 * 2] = rs;
                s_rd[ch * 8 + w4 * 2 + 1] = rq;
            }
        }
        __syncthreads();
        if (t < 6) {
            float s = 0.f, qq = 0.f;
#pragma unroll
            for (int w = 0; w < 4; w++) { s += s_rd[t * 8 + w * 2]; qq += s_rd[t * 8 + w * 2 + 1]; }
            g_part2s[(cb + t) * 64 + n * 2 + half] = s;
            g_part2q[(cb + t) * 64 + n * 2 + half] = qq;
        }
    }

    grid_barrier();

    // ============================ PHASE 3: head ============================
    // 256 blocks: n = bid>>3, chunk = bid&7 (128 fc1 outputs each).
    // Final per-n reduce done by the 8th finisher via atomic ticket (no barrier).
    {
        const int n = bid >> 3;
        const int chunk = bid & 7;
        float* s_q     = smem;            // 128
        float* s_a2    = smem + 128;      // 24
        float* s_c2    = smem + 152;      // 24
        float* s_part  = smem + 176;      // 24*8
        float* s_s     = smem + 368;      // 26 (pad 32)
        float* s_r     = smem + 400;      // 128
        float* s_hpart = smem + 528;      // 256
        float* s_o     = smem + 784;      // 8

        compute_bn24(g_part2s, g_part2q, 64, 1.f / 8192.f, bn2_g, bn2_b, s_a2, s_c2, t);
        if (t >= 192) {
            int j = t - 192;
            s_q[j * 2]     = ques[n * 128 + j * 2];
            s_q[j * 2 + 1] = ques[n * 128 + j * 2 + 1];
        }
        __syncthreads();

        // spatial sums of relu(bn2(y2)) -> s[0..23]; coord sums ~0 -> 0
        if (t < 192) {
            int c = t >> 3, g = t & 7;
            const float* yp = &g_y2[(n * 24 + c) * 256 + g * 32];
            float a = s_a2[c], cc = s_c2[c];
            float acc = 0.f;
#pragma unroll
            for (int i = 0; i < 32; i++) acc += fmaxf(fmaf(a, yp[i], cc), 0.f);
            s_part[c * 8 + g] = acc;
        }
        __syncthreads();
        if (t < 26) {
            float s = 0.f;
            if (t < 24) {
#pragma unroll
                for (int g = 0; g < 8; g++) s += s_part[t * 8 + g];
            }
            s_s[t] = s;
        }
        __syncthreads();

        // relations[j] = 256 * s.(Wi+Wj)[:,j] + 65536 * (q.Wq[:,j] + b_rel[j])
        if (t < 128) {
            const int j = t;
            float r1 = 0.f;
#pragma unroll
            for (int k = 0; k < 26; k++)
                r1 += s_s[k] * (w_rel[k * 128 + j] + w_rel[(26 + k) * 128 + j]);
            float r2 = b_rel[j];
#pragma unroll 8
            for (int q = 0; q < 128; q++)
                r2 = fmaf(s_q[q], w_rel[(52 + q) * 128 + j], r2);
            s_r[j] = 256.f * r1 + 65536.f * r2;
        }
        __syncthreads();

        // fc1 chunk: outputs chunk*128+jj, k split in halves across thread pairs
        {
            const int jj = t & 127, h = t >> 7;
            const int j = chunk * 128 + jj;
            float acc = (h == 0) ? b_fc1[j] : 0.f;
            const float* wp = &w_fc1[(h * 64) * 1024 + j];
            const float* rp = &s_r[h * 64];
#pragma unroll 8
            for (int k = 0; k < 64; k++)
                acc = fmaf(rp[k], wp[k * 1024], acc);
            s_hpart[t] = acc;
        }
        __syncthreads();
        // relu + partial fc2 over this chunk's 128 h values
        {
            float p0 = 0.f, p1 = 0.f;
            if (t < 128) {
                float hv = fmaxf(s_hpart[t] + s_hpart[t + 128], 0.f);
                const int j = chunk * 128 + t;
                p0 = hv * w_fc2[j * 2];
                p1 = hv * w_fc2[j * 2 + 1];
            }
            p0 = warp_sum(p0);
            p1 = warp_sum(p1);
            if (lane == 0 && warp < 4) { s_o[warp * 2] = p0; s_o[warp * 2 + 1] = p1; }
        }
        __syncthreads();
        if (t == 0) {
            float o0 = 0.f, o1 = 0.f;
#pragma unroll
            for (int w = 0; w < 4; w++) { o0 += s_o[w * 2]; o1 += s_o[w * 2 + 1]; }
            g_hpart[(n * 8 + chunk) * 2 + 0] = o0;
            g_hpart[(n * 8 + chunk) * 2 + 1] = o1;
            __threadfence();
            unsigned r = atomicAdd(&g_done[n], 1u);
            if (r == 7) {                      // last chunk for this n: finish
                __threadfence();
                float f0 = b_fc2[0], f1 = b_fc2[1];
#pragma unroll
                for (int c = 0; c < 8; c++) {
                    f0 += g_hpart[(n * 8 + c) * 2 + 0];
                    f1 += g_hpart[(n * 8 + c) * 2 + 1];
                }
                out[n * 2 + 0] = f0;
                out[n * 2 + 1] = f1;
                g_done[n] = 0;                 // self-reset for graph replay
            }
        }
    }
}

// ---------------- launch ----------------
extern "C" void kernel_launch(void* const* d_in, const int* in_sizes, int n_in,
                              void* d_out, int out_size) {
    (void)in_sizes; (void)n_in; (void)out_size;
    const float* image   = (const float*)d_in[0];
    const float* ques    = (const float*)d_in[1];
    const float* conv1_w = (const float*)d_in[2];
    const float* bn1_g   = (const float*)d_in[4];
    const float* bn1_b   = (const float*)d_in[5];
    const float* conv2_w = (const float*)d_in[6];
    const float* bn2_g   = (const float*)d_in[8];
    const float* bn2_b   = (const float*)d_in[9];
    const float* w_rel   = (const float*)d_in[10];
    const float* b_rel   = (const float*)d_in[11];
    const float* w_fc1   = (const float*)d_in[12];
    const float* b_fc1   = (const float*)d_in[13];
    const float* w_fc2   = (const float*)d_in[14];
    const float* b_fc2   = (const float*)d_in[15];
    float* out = (float*)d_out;

    fused_kernel<<<NBLOCKS, 256>>>(image, conv1_w, bn1_g, bn1_b,
                                   conv2_w, bn2_g, bn2_b,
                                   ques, w_rel, b_rel,
                                   w_fc1, b_fc1, w_fc2, b_fc2, out);
}